// round 4
// baseline (speedup 1.0000x reference)
#include <cuda_runtime.h>
#include <cuda_fp16.h>
#include <cstdint>

// ---------------- problem constants ----------------
#define B_ROWS   8192
#define DFEAT    128
#define DKEEP    64
#define TILE     128
#define NTILES   64
#define NTHREADS 256

#define LOG2E 1.4426950408889634f
#define LN2   0.6931471805599453f
#define SHIFTB 32.0f

// smem byte offsets (dynamic smem)
#define SB_X   0
#define SB_Y0  16384
#define SB_Y1  32768
#define SB_RED 49152
#define SMEM_BYTES 49216

// ---------------- scratch (fp16 gathered matrices) ----------------
__device__ __half g_ao [B_ROWS * DKEEP];  // a[:, ai]
__device__ __half g_iao[B_ROWS * DKEEP];  // v[:, ai]
__device__ __half g_io [B_ROWS * DKEEP];  // v[:, ii]
__device__ __half g_aio[B_ROWS * DKEEP];  // a[:, ii]

// ---------------- helpers ----------------
__device__ __forceinline__ uint32_t smem_u32(const void* p) {
    uint32_t a;
    asm("{ .reg .u64 t; cvta.to.shared.u64 t, %1; cvt.u32.u64 %0, t; }" : "=r"(a) : "l"(p));
    return a;
}

__device__ __forceinline__ void cp16(uint32_t dst, const void* src) {
    asm volatile("cp.async.cg.shared.global [%0], [%1], 16;" :: "r"(dst), "l"(src));
}
#define CP_COMMIT() asm volatile("cp.async.commit_group;" ::: "memory")
#define CP_WAIT(n)  asm volatile("cp.async.wait_group %0;" :: "n"(n) : "memory")

__device__ __forceinline__ void ldsm4(uint32_t r[4], uint32_t a) {
    asm volatile("ldmatrix.sync.aligned.m8n8.x4.shared.b16 {%0,%1,%2,%3}, [%4];"
        : "=r"(r[0]), "=r"(r[1]), "=r"(r[2]), "=r"(r[3]) : "r"(a));
}

// fp16-accumulate MMA: C fragment = 2 b32 regs (4 halves)
__device__ __forceinline__ void mma16816_h(uint32_t c[2], const uint32_t a[4],
                                           uint32_t b0, uint32_t b1) {
    asm volatile(
        "mma.sync.aligned.m16n8k16.row.col.f16.f16.f16.f16 "
        "{%0,%1}, {%2,%3,%4,%5}, {%6,%7}, {%0,%1};"
        : "+r"(c[0]), "+r"(c[1])
        : "r"(a[0]), "r"(a[1]), "r"(a[2]), "r"(a[3]), "r"(b0), "r"(b1));
}

__device__ __forceinline__ float ex2f(float t) {
    float e;
    asm("ex2.approx.ftz.f32 %0, %1;" : "=f"(e) : "f"(t));
    return e;
}

// exp-accumulate one quarter (4 frags) of a register tile (fp16-packed)
__device__ __forceinline__ void exp_chunk(const uint32_t (&prev)[16][2], int kk,
                                          bool dtile, int lane, int row0,
                                          float (&ps)[4], float& dg0, float& dg1) {
#pragma unroll
    for (int fi = 0; fi < 4; fi++) {
        const int f = 4 * kk + fi;
        float2 lo = __half22float2(*(const __half2*)&prev[f][0]);  // row0,   cols c0,c0+1
        float2 hi = __half22float2(*(const __half2*)&prev[f][1]);  // row0+8, cols c0,c0+1
        if (dtile) {
            int c0 = 8 * f + 2 * (lane & 3);
            if (c0 == row0)         dg0 = lo.x;
            if (c0 + 1 == row0)     dg0 = lo.y;
            if (c0 == row0 + 8)     dg1 = hi.x;
            if (c0 + 1 == row0 + 8) dg1 = hi.y;
        }
        ps[0] += ex2f(fmaf(lo.x, LOG2E, -SHIFTB));
        ps[1] += ex2f(fmaf(lo.y, LOG2E, -SHIFTB));
        ps[2] += ex2f(fmaf(hi.x, LOG2E, -SHIFTB));
        ps[3] += ex2f(fmaf(hi.y, LOG2E, -SHIFTB));
    }
}

// compute tile j into cur, exp-process prev (tile j-1) interleaved
__device__ __forceinline__ void do_tile(
    int j, int rt, uint32_t sbY, int lane,
    const uint32_t (&A)[4][4],
    const uint32_t (&browoff)[8], const uint32_t (&bxr)[8], int bko,
    uint32_t (&cur)[16][2], uint32_t (&prev)[16][2],
    float (&ps)[4], float& dg0, float& dg1, int row0)
{
#pragma unroll
    for (int f = 0; f < 16; f++) { cur[f][0] = 0u; cur[f][1] = 0u; }
    const bool dtile = ((j - 1) == rt);
#pragma unroll
    for (int kk = 0; kk < 4; kk++) {
        uint32_t Bf[8][4];
#pragma unroll
        for (int nn = 0; nn < 8; nn++) {
            uint32_t addr = sbY + browoff[nn] + (((uint32_t)((kk << 1) + bko) ^ bxr[nn]) << 4);
            ldsm4(Bf[nn], addr);
        }
#pragma unroll
        for (int nn = 0; nn < 8; nn++) {
            mma16816_h(cur[2 * nn],     A[kk], Bf[nn][0], Bf[nn][1]);
            mma16816_h(cur[2 * nn + 1], A[kk], Bf[nn][2], Bf[nn][3]);
        }
        // overlap: MUFU work of previous tile between HMMA batches
        exp_chunk(prev, kk, dtile, lane, row0, ps, dg0, dg1);
    }
}

// ---------------- kernels ----------------
// Index buffers may be int32 (JAX x64 disabled) or int64. Sniff: if every odd
// int32 word of BOTH buffers' first 64 words is zero, values are int64
// (indices < 128 => high words 0). Reads stay within 256B = in-bounds for both
// interpretations. Indices masked &127 so a misdetect can never fault.
__global__ void gather_kernel(const float* __restrict__ a, const float* __restrict__ v,
                              const int* __restrict__ ai32,
                              const int* __restrict__ ii32,
                              float* __restrict__ out, int out_size) {
    __shared__ int sai[DKEEP], sii[DKEEP];
    __shared__ int is64;
    const int tid = threadIdx.x;
    if (blockIdx.x == 0 && tid < out_size) out[tid] = 0.0f;  // fold zero_out
    if (tid == 0) {
        int orr = 0;
#pragma unroll
        for (int k = 0; k < 32; k++) orr |= ai32[2 * k + 1] | ii32[2 * k + 1];
        is64 = (orr == 0) ? 1 : 0;
    }
    __syncthreads();
    if (tid < DKEEP) {
        int step = is64 ? 2 : 1;
        sai[tid] = ai32[tid * step] & (DFEAT - 1);
        sii[tid] = ii32[tid * step] & (DFEAT - 1);
    }
    __syncthreads();

    int t = blockIdx.x * blockDim.x + tid;
    int r = t >> 6, k = t & 63;
    int ia = sai[k];
    int iv = sii[k];
    const float* ar = a + (size_t)r * DFEAT;
    const float* vr = v + (size_t)r * DFEAT;
    g_ao [t] = __float2half(ar[ia]);
    g_iao[t] = __float2half(vr[ia]);
    g_io [t] = __float2half(vr[iv]);
    g_aio[t] = __float2half(ar[iv]);
}

__global__ void __launch_bounds__(NTHREADS, 1)
supcon_main_kernel(float* __restrict__ out) {
    extern __shared__ char smem[];
    const uint32_t sb = smem_u32(smem);
    const int tid  = threadIdx.x;
    const int lane = tid & 31;
    const int wid  = tid >> 5;
    const int m  = blockIdx.x >> 6;   // 0: S_v, 1: S_a
    const int rt = blockIdx.x & 63;   // row tile

    const __half* X = m ? g_aio : g_iao;
    const __half* Y = m ? g_io  : g_ao;
    const char* Yb = (const char*)Y;

    // per-thread swizzled 16B-chunk store offsets (u = tid + k*256)
    uint32_t dsto[4];
#pragma unroll
    for (int k = 0; k < 4; k++) {
        uint32_t u = (uint32_t)tid + k * 256u;
        dsto[k] = (u & ~7u) * 16u + (((u & 7u) ^ ((u >> 3) & 7u)) << 4);
    }

    // prefetch Y tiles 0, 1 via cp.async
#pragma unroll
    for (int k = 0; k < 4; k++)
        cp16(sb + SB_Y0 + dsto[k], Yb + (size_t)(tid + k * 256) * 16);
    CP_COMMIT();
#pragma unroll
    for (int k = 0; k < 4; k++)
        cp16(sb + SB_Y1 + dsto[k], Yb + 16384 + (size_t)(tid + k * 256) * 16);
    CP_COMMIT();

    // X tile -> smem (swizzled)
    {
        const uint4* xg = (const uint4*)(X + (size_t)rt * TILE * DKEEP);
#pragma unroll
        for (int k = 0; k < 4; k++) {
            uint4 val = xg[tid + k * 256];
            *(uint4*)(smem + SB_X + dsto[k]) = val;
        }
    }
    __syncthreads();

    // A fragments (held in registers for the whole kernel)
    uint32_t A[4][4];
    {
        int row = 16 * wid + (lane & 15);
        int kc  = lane >> 4;  // 0/1 -> k halves
#pragma unroll
        for (int kk = 0; kk < 4; kk++) {
            uint32_t chunk = (uint32_t)(kk * 2 + kc);
            uint32_t addr  = sb + SB_X + (uint32_t)row * 128u + ((chunk ^ (uint32_t)(row & 7)) << 4);
            ldsm4(A[kk], addr);
        }
    }

    // B ldmatrix address row parts
    uint32_t browoff[8], bxr[8];
    const int bn  = ((lane >> 4) << 3) + (lane & 7);
    const int bko = (lane >> 3) & 1;
#pragma unroll
    for (int nn = 0; nn < 8; nn++) {
        int nr = 16 * nn + bn;
        browoff[nn] = (uint32_t)nr * 128u;
        bxr[nn] = (uint32_t)(nr & 7);
    }

    uint32_t accC[16][2], accP[16][2];
#pragma unroll
    for (int f = 0; f < 16; f++) {
        accP[f][0] = 0xFC00FC00u;   // -inf halves -> exp = 0 on first tile
        accP[f][1] = 0xFC00FC00u;
    }
    float ps[4] = {0.f, 0.f, 0.f, 0.f};
    float dg0 = 0.f, dg1 = 0.f;
    const int row0 = 16 * wid + (lane >> 2);

    for (int jj = 0; jj < NTILES; jj += 2) {
        // ---- even tile jj : stage 0, cur=accC, prev=accP ----
        CP_WAIT(1);
        __syncthreads();
        do_tile(jj, rt, sb + SB_Y0, lane, A, browoff, bxr, bko,
                accC, accP, ps, dg0, dg1, row0);
        __syncthreads();
        if (jj + 2 < NTILES) {
            const char* src = Yb + (size_t)(jj + 2) * 16384;
#pragma unroll
            for (int k = 0; k < 4; k++)
                cp16(sb + SB_Y0 + dsto[k], src + (size_t)(tid + k * 256) * 16);
            CP_COMMIT();
        }
        // ---- odd tile jj+1 : stage 1, cur=accP, prev=accC ----
        if (jj + 1 == NTILES - 1) { CP_WAIT(0); } else { CP_WAIT(1); }
        __syncthreads();
        do_tile(jj + 1, rt, sb + SB_Y1, lane, A, browoff, bxr, bko,
                accP, accC, ps, dg0, dg1, row0);
        __syncthreads();
        if (jj + 3 < NTILES) {
            const char* src = Yb + (size_t)(jj + 3) * 16384;
#pragma unroll
            for (int k = 0; k < 4; k++)
                cp16(sb + SB_Y1 + dsto[k], src + (size_t)(tid + k * 256) * 16);
            CP_COMMIT();
        }
    }

    // tail: exp-process the last tile (63, sitting in accP)
    {
        const bool dtile = (rt == NTILES - 1);
#pragma unroll
        for (int kk = 0; kk < 4; kk++)
            exp_chunk(accP, kk, dtile, lane, row0, ps, dg0, dg1);
    }

    // ---- reduction ----
    float rs0 = ps[0] + ps[1];
    float rs1 = ps[2] + ps[3];
    rs0 += __shfl_xor_sync(0xffffffffu, rs0, 1);
    rs0 += __shfl_xor_sync(0xffffffffu, rs0, 2);
    rs1 += __shfl_xor_sync(0xffffffffu, rs1, 1);
    rs1 += __shfl_xor_sync(0xffffffffu, rs1, 2);
    dg0 += __shfl_xor_sync(0xffffffffu, dg0, 1);
    dg0 += __shfl_xor_sync(0xffffffffu, dg0, 2);
    dg1 += __shfl_xor_sync(0xffffffffu, dg1, 1);
    dg1 += __shfl_xor_sync(0xffffffffu, dg1, 2);

    float loss = 0.f;
    if ((lane & 3) == 0) {
        float l0, l1;
        asm("lg2.approx.f32 %0, %1;" : "=f"(l0) : "f"(rs0));
        asm("lg2.approx.f32 %0, %1;" : "=f"(l1) : "f"(rs1));
        loss = (l0 + SHIFTB) * LN2 - dg0 + (l1 + SHIFTB) * LN2 - dg1;
    }
#pragma unroll
    for (int o = 4; o < 32; o <<= 1)
        loss += __shfl_xor_sync(0xffffffffu, loss, o);

    float* red = (float*)(smem + SB_RED);
    if (lane == 0) red[wid] = loss;
    __syncthreads();
    if (tid == 0) {
        float t = 0.f;
#pragma unroll
        for (int w = 0; w < 8; w++) t += red[w];
        atomicAdd(out, t * (1.0f / (float)B_ROWS));
    }
}

// ---------------- launch ----------------
extern "C" void kernel_launch(void* const* d_in, const int* in_sizes, int n_in,
                              void* d_out, int out_size) {
    const float* a = (const float*)d_in[0];
    const float* v = (const float*)d_in[1];
    const int* ai = (const int*)d_in[2];
    const int* ii = (const int*)d_in[3];
    float* out = (float*)d_out;

    cudaFuncSetAttribute(supcon_main_kernel,
                         cudaFuncAttributeMaxDynamicSharedMemorySize, SMEM_BYTES);

    gather_kernel<<<(B_ROWS * DKEEP) / 256, 256>>>(a, v, ai, ii, out, out_size);
    supcon_main_kernel<<<128, NTHREADS, SMEM_BYTES>>>(out);
}

// round 5
// speedup vs baseline: 1.0677x; 1.0677x over previous
#include <cuda_runtime.h>
#include <cuda_fp16.h>
#include <cstdint>

// ---------------- problem constants ----------------
#define B_ROWS   8192
#define DFEAT    128
#define DKEEP    64
#define TILE     128
#define NTILES   64
#define NTHREADS 512

#define LOG2E 1.4426950408889634f
#define LN2   0.6931471805599453f
#define SHIFTB 32.0f

// smem byte offsets (dynamic smem)
#define SB_X    0
#define SB_Y0   16384
#define SB_Y1   32768
#define SB_RSUM0 49152            // float[128]
#define SB_RSUM1 (49152+512)
#define SB_DSUM0 (49152+1024)
#define SB_DSUM1 (49152+1536)
#define SB_WRED  (49152+2048)     // float[4]
#define SMEM_BYTES (49152+2112)

// ---------------- scratch (fp16 gathered matrices) ----------------
__device__ __half g_ao [B_ROWS * DKEEP];  // a[:, ai]
__device__ __half g_iao[B_ROWS * DKEEP];  // v[:, ai]
__device__ __half g_io [B_ROWS * DKEEP];  // v[:, ii]
__device__ __half g_aio[B_ROWS * DKEEP];  // a[:, ii]

// ---------------- helpers ----------------
__device__ __forceinline__ uint32_t smem_u32(const void* p) {
    uint32_t a;
    asm("{ .reg .u64 t; cvta.to.shared.u64 t, %1; cvt.u32.u64 %0, t; }" : "=r"(a) : "l"(p));
    return a;
}

__device__ __forceinline__ void cp16(uint32_t dst, const void* src) {
    asm volatile("cp.async.cg.shared.global [%0], [%1], 16;" :: "r"(dst), "l"(src));
}
#define CP_COMMIT() asm volatile("cp.async.commit_group;" ::: "memory")
#define CP_WAIT(n)  asm volatile("cp.async.wait_group %0;" :: "n"(n) : "memory")

__device__ __forceinline__ void ldsm4(uint32_t r[4], uint32_t a) {
    asm volatile("ldmatrix.sync.aligned.m8n8.x4.shared.b16 {%0,%1,%2,%3}, [%4];"
        : "=r"(r[0]), "=r"(r[1]), "=r"(r[2]), "=r"(r[3]) : "r"(a));
}

// fp16-accumulate MMA: C fragment = 2 b32 regs (4 halves)
__device__ __forceinline__ void mma16816_h(uint32_t c[2], const uint32_t a[4],
                                           uint32_t b0, uint32_t b1) {
    asm volatile(
        "mma.sync.aligned.m16n8k16.row.col.f16.f16.f16.f16 "
        "{%0,%1}, {%2,%3,%4,%5}, {%6,%7}, {%0,%1};"
        : "+r"(c[0]), "+r"(c[1])
        : "r"(a[0]), "r"(a[1]), "r"(a[2]), "r"(a[3]), "r"(b0), "r"(b1));
}

__device__ __forceinline__ float ex2f(float t) {
    float e;
    asm("ex2.approx.ftz.f32 %0, %1;" : "=f"(e) : "f"(t));
    return e;
}

// exp-accumulate 2 frags (f = 2*kk, 2*kk+1) of an 8-frag register strip
__device__ __forceinline__ void exp_chunk(const uint32_t (&prev)[8][2], int kk,
                                          bool dtile, int lane, int row0, int colbase,
                                          float (&ps)[4], float& dg0, float& dg1) {
#pragma unroll
    for (int fi = 0; fi < 2; fi++) {
        const int f = 2 * kk + fi;
        float2 lo = __half22float2(*(const __half2*)&prev[f][0]);  // row0
        float2 hi = __half22float2(*(const __half2*)&prev[f][1]);  // row0+8
        if (dtile) {
            int c0 = colbase + 8 * f + 2 * (lane & 3);
            if (c0 == row0)         dg0 = lo.x;
            if (c0 + 1 == row0)     dg0 = lo.y;
            if (c0 == row0 + 8)     dg1 = hi.x;
            if (c0 + 1 == row0 + 8) dg1 = hi.y;
        }
        ps[0] += ex2f(fmaf(lo.x, LOG2E, -SHIFTB));
        ps[1] += ex2f(fmaf(lo.y, LOG2E, -SHIFTB));
        ps[2] += ex2f(fmaf(hi.x, LOG2E, -SHIFTB));
        ps[3] += ex2f(fmaf(hi.y, LOG2E, -SHIFTB));
    }
}

// compute tile j into cur (16 rows x 64 cols strip), exp-process prev interleaved
__device__ __forceinline__ void do_tile(
    int j, int rt, uint32_t sbY, int lane,
    const uint32_t (&A)[4][4],
    const uint32_t (&browoff)[4], const uint32_t (&bxr)[4], int bko,
    uint32_t (&cur)[8][2], uint32_t (&prev)[8][2],
    float (&ps)[4], float& dg0, float& dg1, int row0, int colbase)
{
#pragma unroll
    for (int f = 0; f < 8; f++) { cur[f][0] = 0u; cur[f][1] = 0u; }
    const bool dtile = ((j - 1) == rt);
#pragma unroll
    for (int kk = 0; kk < 4; kk++) {
        uint32_t Bf[4][4];
#pragma unroll
        for (int nn = 0; nn < 4; nn++) {
            uint32_t addr = sbY + browoff[nn] + (((uint32_t)((kk << 1) + bko) ^ bxr[nn]) << 4);
            ldsm4(Bf[nn], addr);
        }
#pragma unroll
        for (int nn = 0; nn < 4; nn++) {
            mma16816_h(cur[2 * nn],     A[kk], Bf[nn][0], Bf[nn][1]);
            mma16816_h(cur[2 * nn + 1], A[kk], Bf[nn][2], Bf[nn][3]);
        }
        // overlap: MUFU work of previous tile between HMMA batches
        exp_chunk(prev, kk, dtile, lane, row0, colbase, ps, dg0, dg1);
    }
}

// ---------------- kernels ----------------
// Index buffers may be int32 (JAX x64 disabled) or int64. Sniff: if every odd
// int32 word of BOTH buffers' first 64 words is zero, values are int64
// (indices < 128 => high words 0). Reads stay within 256B = in-bounds for both
// interpretations. Indices masked &127 so a misdetect can never fault.
__global__ void gather_kernel(const float* __restrict__ a, const float* __restrict__ v,
                              const int* __restrict__ ai32,
                              const int* __restrict__ ii32,
                              float* __restrict__ out, int out_size) {
    __shared__ int sai[DKEEP], sii[DKEEP];
    __shared__ int is64;
    const int tid = threadIdx.x;
    if (blockIdx.x == 0 && tid < out_size) out[tid] = 0.0f;  // fold zero_out
    if (tid == 0) {
        int orr = 0;
#pragma unroll
        for (int k = 0; k < 32; k++) orr |= ai32[2 * k + 1] | ii32[2 * k + 1];
        is64 = (orr == 0) ? 1 : 0;
    }
    __syncthreads();
    if (tid < DKEEP) {
        int step = is64 ? 2 : 1;
        sai[tid] = ai32[tid * step] & (DFEAT - 1);
        sii[tid] = ii32[tid * step] & (DFEAT - 1);
    }
    __syncthreads();

    int t = blockIdx.x * blockDim.x + tid;
    int r = t >> 6, k = t & 63;
    int ia = sai[k];
    int iv = sii[k];
    const float* ar = a + (size_t)r * DFEAT;
    const float* vr = v + (size_t)r * DFEAT;
    g_ao [t] = __float2half(ar[ia]);
    g_iao[t] = __float2half(vr[ia]);
    g_io [t] = __float2half(vr[iv]);
    g_aio[t] = __float2half(ar[iv]);
}

__global__ void __launch_bounds__(NTHREADS, 1)
supcon_main_kernel(float* __restrict__ out) {
    extern __shared__ char smem[];
    const uint32_t sb = smem_u32(smem);
    const int tid  = threadIdx.x;
    const int lane = tid & 31;
    const int wid  = tid >> 5;
    const int rg   = wid & 7;        // row group: rows 16*rg .. 16*rg+15
    const int ch   = wid >> 3;       // column half: cols 64*ch .. 64*ch+63
    const int m  = blockIdx.x >> 6;  // 0: S_v, 1: S_a
    const int rt = blockIdx.x & 63;  // row tile

    const __half* X = m ? g_aio : g_iao;
    const __half* Y = m ? g_io  : g_ao;
    const char* Yb = (const char*)Y;

    // per-thread swizzled 16B-chunk store offsets (u = tid + k*512)
    uint32_t dsto[2];
#pragma unroll
    for (int k = 0; k < 2; k++) {
        uint32_t u = (uint32_t)tid + k * 512u;
        dsto[k] = (u & ~7u) * 16u + (((u & 7u) ^ ((u >> 3) & 7u)) << 4);
    }

    // prefetch Y tiles 0, 1 via cp.async
#pragma unroll
    for (int k = 0; k < 2; k++)
        cp16(sb + SB_Y0 + dsto[k], Yb + (size_t)(tid + k * 512) * 16);
    CP_COMMIT();
#pragma unroll
    for (int k = 0; k < 2; k++)
        cp16(sb + SB_Y1 + dsto[k], Yb + 16384 + (size_t)(tid + k * 512) * 16);
    CP_COMMIT();

    // X tile -> smem (swizzled)
    {
        const uint4* xg = (const uint4*)(X + (size_t)rt * TILE * DKEEP);
#pragma unroll
        for (int k = 0; k < 2; k++) {
            uint4 val = xg[tid + k * 512];
            *(uint4*)(smem + SB_X + dsto[k]) = val;
        }
    }
    __syncthreads();

    // A fragments (held in registers for the whole kernel)
    uint32_t A[4][4];
    {
        int row = 16 * rg + (lane & 15);
        int kc  = lane >> 4;  // 0/1 -> k halves
#pragma unroll
        for (int kk = 0; kk < 4; kk++) {
            uint32_t chunk = (uint32_t)(kk * 2 + kc);
            uint32_t addr  = sb + SB_X + (uint32_t)row * 128u + ((chunk ^ (uint32_t)(row & 7)) << 4);
            ldsm4(A[kk], addr);
        }
    }

    // B ldmatrix address row parts (4 n-blocks of 16 cols in this warp's half)
    uint32_t browoff[4], bxr[4];
    const int bn  = ((lane >> 4) << 3) + (lane & 7);
    const int bko = (lane >> 3) & 1;
#pragma unroll
    for (int nn = 0; nn < 4; nn++) {
        int nr = 16 * (4 * ch + nn) + bn;
        browoff[nn] = (uint32_t)nr * 128u;
        bxr[nn] = (uint32_t)(nr & 7);
    }

    uint32_t accC[8][2], accP[8][2];
#pragma unroll
    for (int f = 0; f < 8; f++) {
        accP[f][0] = 0xFC00FC00u;   // -inf halves -> exp = 0 on first tile
        accP[f][1] = 0xFC00FC00u;
    }
    float ps[4] = {0.f, 0.f, 0.f, 0.f};
    float dg0 = 0.f, dg1 = 0.f;
    const int row0 = 16 * rg + (lane >> 2);
    const int colbase = 64 * ch;

    for (int jj = 0; jj < NTILES; jj += 2) {
        // ---- even tile jj : stage 0, cur=accC, prev=accP ----
        CP_WAIT(1);
        __syncthreads();
        do_tile(jj, rt, sb + SB_Y0, lane, A, browoff, bxr, bko,
                accC, accP, ps, dg0, dg1, row0, colbase);
        __syncthreads();
        if (jj + 2 < NTILES) {
            const char* src = Yb + (size_t)(jj + 2) * 16384;
#pragma unroll
            for (int k = 0; k < 2; k++)
                cp16(sb + SB_Y0 + dsto[k], src + (size_t)(tid + k * 512) * 16);
            CP_COMMIT();
        }
        // ---- odd tile jj+1 : stage 1, cur=accP, prev=accC ----
        if (jj + 1 == NTILES - 1) { CP_WAIT(0); } else { CP_WAIT(1); }
        __syncthreads();
        do_tile(jj + 1, rt, sb + SB_Y1, lane, A, browoff, bxr, bko,
                accP, accC, ps, dg0, dg1, row0, colbase);
        __syncthreads();
        if (jj + 3 < NTILES) {
            const char* src = Yb + (size_t)(jj + 3) * 16384;
#pragma unroll
            for (int k = 0; k < 2; k++)
                cp16(sb + SB_Y1 + dsto[k], src + (size_t)(tid + k * 512) * 16);
            CP_COMMIT();
        }
    }

    // tail: exp-process the last tile (63, sitting in accP)
    {
        const bool dtile = (rt == NTILES - 1);
#pragma unroll
        for (int kk = 0; kk < 4; kk++)
            exp_chunk(accP, kk, dtile, lane, row0, colbase, ps, dg0, dg1);
    }

    // ---- reduction: half-row sums + diag into smem planes ----
    float rs0 = ps[0] + ps[1];             // row0,   this 64-col half
    float rs1 = ps[2] + ps[3];             // row0+8, this 64-col half
    rs0 += __shfl_xor_sync(0xffffffffu, rs0, 1);
    rs0 += __shfl_xor_sync(0xffffffffu, rs0, 2);
    rs1 += __shfl_xor_sync(0xffffffffu, rs1, 1);
    rs1 += __shfl_xor_sync(0xffffffffu, rs1, 2);
    dg0 += __shfl_xor_sync(0xffffffffu, dg0, 1);
    dg0 += __shfl_xor_sync(0xffffffffu, dg0, 2);
    dg1 += __shfl_xor_sync(0xffffffffu, dg1, 1);
    dg1 += __shfl_xor_sync(0xffffffffu, dg1, 2);

    float* rsum = (float*)(smem + (ch ? SB_RSUM1 : SB_RSUM0));
    float* dsum = (float*)(smem + (ch ? SB_DSUM1 : SB_DSUM0));
    if ((lane & 3) == 0) {
        rsum[row0]     = rs0;
        rsum[row0 + 8] = rs1;
        dsum[row0]     = dg0;
        dsum[row0 + 8] = dg1;
    }
    __syncthreads();

    float loss = 0.f;
    if (tid < 128) {
        float tot = ((float*)(smem + SB_RSUM0))[tid] + ((float*)(smem + SB_RSUM1))[tid];
        float dg  = ((float*)(smem + SB_DSUM0))[tid] + ((float*)(smem + SB_DSUM1))[tid];
        float lg;
        asm("lg2.approx.f32 %0, %1;" : "=f"(lg) : "f"(tot));
        loss = (lg + SHIFTB) * LN2 - dg;
#pragma unroll
        for (int o = 1; o < 32; o <<= 1)
            loss += __shfl_xor_sync(0xffffffffu, loss, o);
        if (lane == 0) ((float*)(smem + SB_WRED))[wid] = loss;
    }
    __syncthreads();
    if (tid == 0) {
        float* wr = (float*)(smem + SB_WRED);
        atomicAdd(out, (wr[0] + wr[1] + wr[2] + wr[3]) * (1.0f / (float)B_ROWS));
    }
}

// ---------------- launch ----------------
extern "C" void kernel_launch(void* const* d_in, const int* in_sizes, int n_in,
                              void* d_out, int out_size) {
    const float* a = (const float*)d_in[0];
    const float* v = (const float*)d_in[1];
    const int* ai = (const int*)d_in[2];
    const int* ii = (const int*)d_in[3];
    float* out = (float*)d_out;

    cudaFuncSetAttribute(supcon_main_kernel,
                         cudaFuncAttributeMaxDynamicSharedMemorySize, SMEM_BYTES);

    gather_kernel<<<(B_ROWS * DKEEP) / 256, 256>>>(a, v, ai, ii, out, out_size);
    supcon_main_kernel<<<128, NTHREADS, SMEM_BYTES>>>(out);
}

// round 6
// speedup vs baseline: 1.0932x; 1.0238x over previous
#include <cuda_runtime.h>
#include <cuda_fp16.h>
#include <cstdint>

// ---------------- problem constants ----------------
#define B_ROWS   8192
#define DFEAT    128
#define DKEEP    64
#define TILE     128
#define NTILES   64
#define NTHREADS 512

#define LOG2E 1.4426950408889634f
#define LN2   0.6931471805599453f
#define SHIFTB 32.0f

// smem byte offsets (dynamic smem)
#define SB_X     0
#define SB_Y0    16384
#define SB_Y1    32768
#define SB_RSUM0 49152            // float[128]
#define SB_RSUM1 (49152+512)
#define SB_WRED  (49152+1024)     // float[4]
#define SMEM_BYTES (49152+1088)

// ---------------- scratch (fp16 gathered matrices) ----------------
__device__ __half g_ao [B_ROWS * DKEEP];  // a[:, ai]
__device__ __half g_iao[B_ROWS * DKEEP];  // v[:, ai]
__device__ __half g_io [B_ROWS * DKEEP];  // v[:, ii]
__device__ __half g_aio[B_ROWS * DKEEP];  // a[:, ii]

// ---------------- helpers ----------------
__device__ __forceinline__ uint32_t smem_u32(const void* p) {
    uint32_t a;
    asm("{ .reg .u64 t; cvta.to.shared.u64 t, %1; cvt.u32.u64 %0, t; }" : "=r"(a) : "l"(p));
    return a;
}

__device__ __forceinline__ void cp16(uint32_t dst, const void* src) {
    asm volatile("cp.async.cg.shared.global [%0], [%1], 16;" :: "r"(dst), "l"(src));
}
#define CP_COMMIT() asm volatile("cp.async.commit_group;" ::: "memory")
#define CP_WAIT(n)  asm volatile("cp.async.wait_group %0;" :: "n"(n) : "memory")

__device__ __forceinline__ void ldsm4(uint32_t r[4], uint32_t a) {
    asm volatile("ldmatrix.sync.aligned.m8n8.x4.shared.b16 {%0,%1,%2,%3}, [%4];"
        : "=r"(r[0]), "=r"(r[1]), "=r"(r[2]), "=r"(r[3]) : "r"(a));
}

// fp16-accumulate MMA: C fragment = 2 b32 regs (4 halves)
__device__ __forceinline__ void mma16816_h(uint32_t c[2], const uint32_t a[4],
                                           uint32_t b0, uint32_t b1) {
    asm volatile(
        "mma.sync.aligned.m16n8k16.row.col.f16.f16.f16.f16 "
        "{%0,%1}, {%2,%3,%4,%5}, {%6,%7}, {%0,%1};"
        : "+r"(c[0]), "+r"(c[1])
        : "r"(a[0]), "r"(a[1]), "r"(a[2]), "r"(a[3]), "r"(b0), "r"(b1));
}

__device__ __forceinline__ float ex2f(float t) {
    float e;
    asm("ex2.approx.ftz.f32 %0, %1;" : "=f"(e) : "f"(t));
    return e;
}

// exp-accumulate one half2 (2 elements)
__device__ __forceinline__ void exp_pair(uint32_t h2, float& pa, float& pb) {
    float2 f = __half22float2(*(const __half2*)&h2);
    pa += ex2f(fmaf(f.x, LOG2E, -SHIFTB));
    pb += ex2f(fmaf(f.y, LOG2E, -SHIFTB));
}

// compute tile j into cur (16 rows x 64 cols strip); exp-process prev,
// finely interleaved between MMA pairs to co-feed tensor + MUFU pipes.
__device__ __forceinline__ void do_tile(
    uint32_t sbY,
    const uint32_t (&A)[4][4],
    const uint32_t (&browoff)[4], const uint32_t (&bxr)[4], int bko,
    uint32_t (&cur)[8][2], uint32_t (&prev)[8][2],
    float (&ps)[4])
{
#pragma unroll
    for (int f = 0; f < 8; f++) { cur[f][0] = 0u; cur[f][1] = 0u; }
#pragma unroll
    for (int kk = 0; kk < 4; kk++) {
        uint32_t Bf[4][4];
#pragma unroll
        for (int nn = 0; nn < 4; nn++) {
            uint32_t addr = sbY + browoff[nn] + (((uint32_t)((kk << 1) + bko) ^ bxr[nn]) << 4);
            ldsm4(Bf[nn], addr);
        }
        mma16816_h(cur[0], A[kk], Bf[0][0], Bf[0][1]);
        mma16816_h(cur[1], A[kk], Bf[0][2], Bf[0][3]);
        exp_pair(prev[2 * kk][0], ps[0], ps[1]);
        mma16816_h(cur[2], A[kk], Bf[1][0], Bf[1][1]);
        mma16816_h(cur[3], A[kk], Bf[1][2], Bf[1][3]);
        exp_pair(prev[2 * kk][1], ps[2], ps[3]);
        mma16816_h(cur[4], A[kk], Bf[2][0], Bf[2][1]);
        mma16816_h(cur[5], A[kk], Bf[2][2], Bf[2][3]);
        exp_pair(prev[2 * kk + 1][0], ps[0], ps[1]);
        mma16816_h(cur[6], A[kk], Bf[3][0], Bf[3][1]);
        mma16816_h(cur[7], A[kk], Bf[3][2], Bf[3][3]);
        exp_pair(prev[2 * kk + 1][1], ps[2], ps[3]);
    }
}

// ---------------- kernels ----------------
// Index buffers may be int32 (JAX x64 disabled) or int64. Sniff: if every odd
// int32 word of BOTH buffers' first 64 words is zero, values are int64
// (indices < 128 => high words 0). Reads stay within 256B = in-bounds for both
// interpretations. Indices masked &127 so a misdetect can never fault.
__global__ void gather_kernel(const float* __restrict__ a, const float* __restrict__ v,
                              const int* __restrict__ ai32,
                              const int* __restrict__ ii32,
                              float* __restrict__ out, int out_size) {
    __shared__ int sai[DKEEP], sii[DKEEP];
    __shared__ int is64;
    const int tid = threadIdx.x;
    if (blockIdx.x == 0 && tid < out_size) out[tid] = 0.0f;  // fold zero_out
    if (tid == 0) {
        int orr = 0;
#pragma unroll
        for (int k = 0; k < 32; k++) orr |= ai32[2 * k + 1] | ii32[2 * k + 1];
        is64 = (orr == 0) ? 1 : 0;
    }
    __syncthreads();
    if (tid < DKEEP) {
        int step = is64 ? 2 : 1;
        sai[tid] = ai32[tid * step] & (DFEAT - 1);
        sii[tid] = ii32[tid * step] & (DFEAT - 1);
    }
    __syncthreads();

    int t = blockIdx.x * blockDim.x + tid;
    int r = t >> 6, k = t & 63;
    int ia = sai[k];
    int iv = sii[k];
    const float* ar = a + (size_t)r * DFEAT;
    const float* vr = v + (size_t)r * DFEAT;
    g_ao [t] = __float2half(ar[ia]);
    g_iao[t] = __float2half(vr[ia]);
    g_io [t] = __float2half(vr[iv]);
    g_aio[t] = __float2half(ar[iv]);
}

__global__ void __launch_bounds__(NTHREADS, 1)
supcon_main_kernel(float* __restrict__ out) {
    extern __shared__ char smem[];
    const uint32_t sb = smem_u32(smem);
    const int tid  = threadIdx.x;
    const int lane = tid & 31;
    const int wid  = tid >> 5;
    const int rg   = wid & 7;        // row group: rows 16*rg .. 16*rg+15
    const int ch   = wid >> 3;       // column half: cols 64*ch .. 64*ch+63
    const int m  = blockIdx.x >> 6;  // 0: S_v, 1: S_a
    const int rt = blockIdx.x & 63;  // row tile

    const __half* X = m ? g_aio : g_iao;
    const __half* Y = m ? g_io  : g_ao;
    const char* Yb = (const char*)Y;

    // per-thread swizzled 16B-chunk store offsets (u = tid + k*512)
    uint32_t dsto[2];
#pragma unroll
    for (int k = 0; k < 2; k++) {
        uint32_t u = (uint32_t)tid + k * 512u;
        dsto[k] = (u & ~7u) * 16u + (((u & 7u) ^ ((u >> 3) & 7u)) << 4);
    }

    // prefetch Y tiles 0, 1 via cp.async
#pragma unroll
    for (int k = 0; k < 2; k++)
        cp16(sb + SB_Y0 + dsto[k], Yb + (size_t)(tid + k * 512) * 16);
    CP_COMMIT();
#pragma unroll
    for (int k = 0; k < 2; k++)
        cp16(sb + SB_Y1 + dsto[k], Yb + 16384 + (size_t)(tid + k * 512) * 16);
    CP_COMMIT();

    // X tile -> smem (swizzled)
    {
        const uint4* xg = (const uint4*)(X + (size_t)rt * TILE * DKEEP);
#pragma unroll
        for (int k = 0; k < 2; k++) {
            uint4 val = xg[tid + k * 512];
            *(uint4*)(smem + SB_X + dsto[k]) = val;
        }
    }
    __syncthreads();

    // A fragments (held in registers for the whole kernel)
    uint32_t A[4][4];
    {
        int row = 16 * rg + (lane & 15);
        int kc  = lane >> 4;  // 0/1 -> k halves
#pragma unroll
        for (int kk = 0; kk < 4; kk++) {
            uint32_t chunk = (uint32_t)(kk * 2 + kc);
            uint32_t addr  = sb + SB_X + (uint32_t)row * 128u + ((chunk ^ (uint32_t)(row & 7)) << 4);
            ldsm4(A[kk], addr);
        }
    }

    // B ldmatrix address row parts (4 n-blocks of 16 cols in this warp's half)
    uint32_t browoff[4], bxr[4];
    const int bn  = ((lane >> 4) << 3) + (lane & 7);
    const int bko = (lane >> 3) & 1;
#pragma unroll
    for (int nn = 0; nn < 4; nn++) {
        int nr = 16 * (4 * ch + nn) + bn;
        browoff[nn] = (uint32_t)nr * 128u;
        bxr[nn] = (uint32_t)(nr & 7);
    }

    uint32_t accC[8][2], accP[8][2];
#pragma unroll
    for (int f = 0; f < 8; f++) {
        accP[f][0] = 0xFC00FC00u;   // -inf halves -> exp = 0 on first tile
        accP[f][1] = 0xFC00FC00u;
    }
    float ps[4] = {0.f, 0.f, 0.f, 0.f};

    for (int jj = 0; jj < NTILES; jj += 2) {
        // ---- even tile jj : stage 0, cur=accC, prev=accP ----
        CP_WAIT(1);
        __syncthreads();
        do_tile(sb + SB_Y0, A, browoff, bxr, bko, accC, accP, ps);
        __syncthreads();
        if (jj + 2 < NTILES) {
            const char* src = Yb + (size_t)(jj + 2) * 16384;
#pragma unroll
            for (int k = 0; k < 2; k++)
                cp16(sb + SB_Y0 + dsto[k], src + (size_t)(tid + k * 512) * 16);
            CP_COMMIT();
        }
        // ---- odd tile jj+1 : stage 1, cur=accP, prev=accC ----
        if (jj + 1 == NTILES - 1) { CP_WAIT(0); } else { CP_WAIT(1); }
        __syncthreads();
        do_tile(sb + SB_Y1, A, browoff, bxr, bko, accP, accC, ps);
        __syncthreads();
        if (jj + 3 < NTILES) {
            const char* src = Yb + (size_t)(jj + 3) * 16384;
#pragma unroll
            for (int k = 0; k < 2; k++)
                cp16(sb + SB_Y1 + dsto[k], src + (size_t)(tid + k * 512) * 16);
            CP_COMMIT();
        }
    }

    // tail: exp-process the last tile (63, sitting in accP)
#pragma unroll
    for (int kk = 0; kk < 4; kk++) {
        exp_pair(accP[2 * kk][0],     ps[0], ps[1]);
        exp_pair(accP[2 * kk][1],     ps[2], ps[3]);
        exp_pair(accP[2 * kk + 1][0], ps[0], ps[1]);
        exp_pair(accP[2 * kk + 1][1], ps[2], ps[3]);
    }

    // ---- reduction: half-row sums into smem planes ----
    float rs0 = ps[0] + ps[1];             // row0,   this 64-col half
    float rs1 = ps[2] + ps[3];             // row0+8, this 64-col half
    rs0 += __shfl_xor_sync(0xffffffffu, rs0, 1);
    rs0 += __shfl_xor_sync(0xffffffffu, rs0, 2);
    rs1 += __shfl_xor_sync(0xffffffffu, rs1, 1);
    rs1 += __shfl_xor_sync(0xffffffffu, rs1, 2);

    const int row0 = 16 * rg + (lane >> 2);
    float* rsum = (float*)(smem + (ch ? SB_RSUM1 : SB_RSUM0));
    if ((lane & 3) == 0) {
        rsum[row0]     = rs0;
        rsum[row0 + 8] = rs1;
    }
    __syncthreads();

    // ---- diag recompute (f32) + final loss ----
    float loss = 0.f;
    if (tid < 128) {
        const uint4* xr = (const uint4*)(X + (size_t)(rt * TILE + tid) * DKEEP);
        const uint4* yr = (const uint4*)(Y + (size_t)(rt * TILE + tid) * DKEEP);
        float dg = 0.f;
#pragma unroll
        for (int i = 0; i < 8; i++) {
            uint4 xv = xr[i];
            uint4 yv = yr[i];
            const uint32_t* xw = (const uint32_t*)&xv;
            const uint32_t* yw = (const uint32_t*)&yv;
#pragma unroll
            for (int w = 0; w < 4; w++) {
                float2 xf = __half22float2(*(const __half2*)&xw[w]);
                float2 yf = __half22float2(*(const __half2*)&yw[w]);
                dg = fmaf(xf.x, yf.x, dg);
                dg = fmaf(xf.y, yf.y, dg);
            }
        }
        float tot = ((float*)(smem + SB_RSUM0))[tid] + ((float*)(smem + SB_RSUM1))[tid];
        float lg;
        asm("lg2.approx.f32 %0, %1;" : "=f"(lg) : "f"(tot));
        loss = (lg + SHIFTB) * LN2 - dg;
#pragma unroll
        for (int o = 1; o < 32; o <<= 1)
            loss += __shfl_xor_sync(0xffffffffu, loss, o);
        if (lane == 0) ((float*)(smem + SB_WRED))[wid] = loss;
    }
    __syncthreads();
    if (tid == 0) {
        float* wr = (float*)(smem + SB_WRED);
        atomicAdd(out, (wr[0] + wr[1] + wr[2] + wr[3]) * (1.0f / (float)B_ROWS));
    }
}

// ---------------- launch ----------------
extern "C" void kernel_launch(void* const* d_in, const int* in_sizes, int n_in,
                              void* d_out, int out_size) {
    const float* a = (const float*)d_in[0];
    const float* v = (const float*)d_in[1];
    const int* ai = (const int*)d_in[2];
    const int* ii = (const int*)d_in[3];
    float* out = (float*)d_out;

    cudaFuncSetAttribute(supcon_main_kernel,
                         cudaFuncAttributeMaxDynamicSharedMemorySize, SMEM_BYTES);

    gather_kernel<<<(B_ROWS * DKEEP) / 256, 256>>>(a, v, ai, ii, out, out_size);
    supcon_main_kernel<<<128, NTHREADS, SMEM_BYTES>>>(out);
}